// round 4
// baseline (speedup 1.0000x reference)
#include <cuda_runtime.h>

// LSTM scan: T=2048, B=2048, IN=5, H=10.
// R3: pull all h-independent work off the recurrent chain.
//  - x-part gate partials (bias + x*Wih) computed at prefetch time (PF=8 steps
//    ahead) into f32x2 accumulators; recurrent chain is only h*Whh + acts.
//  - incremental prefetch pointer (no per-step 64-bit address math / clamp).
//  - warp-confined batches (3 per warp), h exchanged via SHFL; MUFU.TANH acts.

#define T_STEPS 2048
#define BATCH   2048
#define IN_DIM  5
#define HID     10
#define BPW     3                              // batches per warp (30 lanes)
#define NBLOCKS ((BATCH + BPW - 1) / BPW)      // 683 one-warp blocks
#define PF      8                              // prefetch depth (divides T)

typedef unsigned long long u64;

__device__ __forceinline__ u64 pack2(float lo, float hi) {
    u64 r;
    asm("mov.b64 %0, {%1, %2};" : "=l"(r) : "f"(lo), "f"(hi));
    return r;
}
__device__ __forceinline__ void unpack2(u64 v, float& lo, float& hi) {
    asm("mov.b64 {%0, %1}, %2;" : "=f"(lo), "=f"(hi) : "l"(v));
}
__device__ __forceinline__ u64 ffma2(u64 a, u64 b, u64 c) {
    u64 d;
    asm("fma.rn.f32x2 %0, %1, %2, %3;" : "=l"(d) : "l"(a), "l"(b), "l"(c));
    return d;
}
__device__ __forceinline__ float tanha(float z) {
    float r;
    asm("tanh.approx.f32 %0, %1;" : "=f"(r) : "f"(z));
    return r;
}
// sigmoid(z) = 0.5 + 0.5*tanh(0.5*z)
__device__ __forceinline__ float fsig(float z) {
    return fmaf(0.5f, tanha(0.5f * z), 0.5f);
}

__global__ void __launch_bounds__(32, 1) lstm_scan_kernel(
    const float* __restrict__ x,     // [T, B, IN]
    const float* __restrict__ hx0,   // [B, H]
    const float* __restrict__ cx0,   // [B, H]
    const float* __restrict__ Wih,   // [4H, IN]
    const float* __restrict__ Whh,   // [4H, H]
    const float* __restrict__ bih,   // [4H]
    const float* __restrict__ bhh,   // [4H]
    float* __restrict__ out)         // [T*B, H]
{
    const int lane = threadIdx.x;
    const int g    = lane / HID;          // batch slot within warp (0..3)
    const int h    = lane % HID;          // hidden unit 0..9
    const int base = g * HID;             // first lane of this batch's group

    const int  b_raw  = blockIdx.x * BPW + g;
    const bool active = (g < BPW) && (b_raw < BATCH);
    const int  b      = active ? b_raw : (BATCH - 1);   // clamp: safe loads

    // Weights: x-part pairs (x0x1, x2x3, x4|pad) and h-part pairs (5 x f32x2).
    u64 wpx[4][3], wph[4][5];
    float bias[4];
#pragma unroll
    for (int q = 0; q < 4; q++) {
        const int r = q * HID + h;
        float wv[6];
#pragma unroll
        for (int k = 0; k < IN_DIM; k++) wv[k] = Wih[r * IN_DIM + k];
        wv[5] = 0.0f;                                    // pad
#pragma unroll
        for (int p = 0; p < 3; p++) wpx[q][p] = pack2(wv[2 * p], wv[2 * p + 1]);
#pragma unroll
        for (int p = 0; p < 5; p++)
            wph[q][p] = pack2(Whh[r * HID + 2 * p], Whh[r * HID + 2 * p + 1]);
        bias[q] = bih[r] + bhh[r];
    }

    float c    = cx0[(size_t)b * HID + h];
    float hcur = hx0[(size_t)b * HID + h];

    // Prefetch pipeline: axx[d][q] = bias[q] + x(t+d) . Wih_row (as f32x2 acc).
    const size_t xstep = (size_t)BATCH * IN_DIM;         // floats per timestep
    const float* xpf = x + (size_t)b * IN_DIM;           // next row to fetch
    u64 axx[PF][4];
#pragma unroll
    for (int d = 0; d < PF; d++) {
        const float x0 = __ldg(xpf + 0), x1 = __ldg(xpf + 1);
        const float x2 = __ldg(xpf + 2), x3 = __ldg(xpf + 3);
        const float x4 = __ldg(xpf + 4);
        const u64 v0 = pack2(x0, x1), v1 = pack2(x2, x3), v2 = pack2(x4, 0.0f);
#pragma unroll
        for (int q = 0; q < 4; q++) {
            u64 acc = pack2(bias[q], 0.0f);
            acc = ffma2(wpx[q][0], v0, acc);
            acc = ffma2(wpx[q][1], v1, acc);
            acc = ffma2(wpx[q][2], v2, acc);
            axx[d][q] = acc;
        }
        xpf += xstep;
    }

    float* op = out + (size_t)b * HID + h;

#pragma unroll 1
    for (int tc = 0; tc < T_STEPS; tc += PF) {
        const bool do_pf = (tc + PF < T_STEPS);          // uniform
#pragma unroll
        for (int d = 0; d < PF; d++) {
            // Gather this batch's 10 h values from peer lanes (on-chain).
            float hv[HID];
#pragma unroll
            for (int j = 0; j < HID; j++)
                hv[j] = __shfl_sync(0xFFFFFFFFu, hcur, base + j);

            // Prefetch x for step (tc+d+PF) and fold into axx[d] (off-chain).
            u64 nacc[4];
            if (do_pf) {
                const float x0 = __ldg(xpf + 0), x1 = __ldg(xpf + 1);
                const float x2 = __ldg(xpf + 2), x3 = __ldg(xpf + 3);
                const float x4 = __ldg(xpf + 4);
                const u64 v0 = pack2(x0, x1), v1 = pack2(x2, x3),
                          v2 = pack2(x4, 0.0f);
#pragma unroll
                for (int q = 0; q < 4; q++) {
                    u64 acc = pack2(bias[q], 0.0f);
                    acc = ffma2(wpx[q][0], v0, acc);
                    acc = ffma2(wpx[q][1], v1, acc);
                    acc = ffma2(wpx[q][2], v2, acc);
                    nacc[q] = acc;
                }
                xpf += xstep;
            }

            u64 hp[5];
#pragma unroll
            for (int p = 0; p < 5; p++) hp[p] = pack2(hv[2 * p], hv[2 * p + 1]);

            float gate[4];
#pragma unroll
            for (int q = 0; q < 4; q++) {
                u64 acc = axx[d][q];
#pragma unroll
                for (int p = 0; p < 5; p++) acc = ffma2(wph[q][p], hp[p], acc);
                float lo, hi;
                unpack2(acc, lo, hi);
                gate[q] = lo + hi;
            }

            const float is = fsig(gate[0]);
            const float fs = fsig(gate[1]);
            const float gt = tanha(gate[2]);
            const float os = fsig(gate[3]);
            c = fs * c + is * gt;
            const float hn = os * tanha(c);
            hcur = hn;

            if (do_pf) {
#pragma unroll
                for (int q = 0; q < 4; q++) axx[d][q] = nacc[q];
            }

            if (active) *op = hn;            // coalesced within batch group
            op += (size_t)BATCH * HID;
        }
    }
}

extern "C" void kernel_launch(void* const* d_in, const int* in_sizes, int n_in,
                              void* d_out, int out_size) {
    (void)in_sizes; (void)n_in; (void)out_size;
    const float* x   = (const float*)d_in[0];
    const float* hx0 = (const float*)d_in[1];
    const float* cx0 = (const float*)d_in[2];
    const float* Wih = (const float*)d_in[3];
    const float* Whh = (const float*)d_in[4];
    const float* bih = (const float*)d_in[5];
    const float* bhh = (const float*)d_in[6];
    float* out = (float*)d_out;

    lstm_scan_kernel<<<NBLOCKS, 32>>>(x, hx0, cx0, Wih, Whh, bih, bhh, out);
}

// round 7
// speedup vs baseline: 1.6997x; 1.6997x over previous
#include <cuda_runtime.h>

// LSTM scan: T=2048, B=2048, IN=5, H=10.
// R4 = R2 datapath + 4-warp blocks.
//   R2's single-warp blocks put every warp on SMSP0 (wid%4 mapping) -> one
//   scheduler carried ~4.6 warps while 3 idled. 128-thread blocks spread the
//   warps across all 4 SMSPs.
// Datapath (validated in R2): raw-x register ring PF=4 (DRAM latency hidden),
// warp-confined batches (3/warp) exchanged via SHFL, MUFU.TANH activations,
// packed f32x2 FMAs. New: split h-dot into 3+2 chains (shorter critical path).

#define T_STEPS 2048
#define BATCH   2048
#define IN_DIM  5
#define HID     10
#define BPW     3                              // batches per warp (30 lanes)
#define WARPS   4
#define NTHREADS (WARPS * 32)                  // 128
#define BPB     (WARPS * BPW)                  // 12 batches per block
#define NBLOCKS ((BATCH + BPB - 1) / BPB)      // 171
#define PF      4                              // x prefetch depth (divides T)

typedef unsigned long long u64;

__device__ __forceinline__ u64 pack2(float lo, float hi) {
    u64 r;
    asm("mov.b64 %0, {%1, %2};" : "=l"(r) : "f"(lo), "f"(hi));
    return r;
}
__device__ __forceinline__ void unpack2(u64 v, float& lo, float& hi) {
    asm("mov.b64 {%0, %1}, %2;" : "=f"(lo), "=f"(hi) : "l"(v));
}
__device__ __forceinline__ u64 ffma2(u64 a, u64 b, u64 c) {
    u64 d;
    asm("fma.rn.f32x2 %0, %1, %2, %3;" : "=l"(d) : "l"(a), "l"(b), "l"(c));
    return d;
}
__device__ __forceinline__ u64 fmul2(u64 a, u64 b) {
    u64 d;
    asm("mul.rn.f32x2 %0, %1, %2;" : "=l"(d) : "l"(a), "l"(b));
    return d;
}
__device__ __forceinline__ u64 fadd2(u64 a, u64 b) {
    u64 d;
    asm("add.rn.f32x2 %0, %1, %2;" : "=l"(d) : "l"(a), "l"(b));
    return d;
}
__device__ __forceinline__ float tanha(float z) {
    float r;
    asm("tanh.approx.f32 %0, %1;" : "=f"(r) : "f"(z));
    return r;
}
// sigmoid(z) = 0.5 + 0.5*tanh(0.5*z)
__device__ __forceinline__ float fsig(float z) {
    return fmaf(0.5f, tanha(0.5f * z), 0.5f);
}

__global__ void __launch_bounds__(NTHREADS, 1) lstm_scan_kernel(
    const float* __restrict__ x,     // [T, B, IN]
    const float* __restrict__ hx0,   // [B, H]
    const float* __restrict__ cx0,   // [B, H]
    const float* __restrict__ Wih,   // [4H, IN]
    const float* __restrict__ Whh,   // [4H, H]
    const float* __restrict__ bih,   // [4H]
    const float* __restrict__ bhh,   // [4H]
    float* __restrict__ out)         // [T*B, H]
{
    const int lane = threadIdx.x & 31;
    const int warp = threadIdx.x >> 5;
    const int g    = lane / HID;          // batch slot within warp (0..3)
    const int h    = lane % HID;          // hidden unit 0..9
    const int base = g * HID;             // first lane of this batch's group

    const int  b_raw  = blockIdx.x * BPB + warp * BPW + g;
    const bool active = (g < BPW) && (b_raw < BATCH);
    const int  b      = active ? b_raw : (BATCH - 1);   // clamp: safe loads

    // Pack weights for v-layout [x0..x4, 0, h0..h9] (16 slots -> 8 f32x2).
    u64 wp[4][8];
    float bias[4];
#pragma unroll
    for (int q = 0; q < 4; q++) {
        const int r = q * HID + h;
        float wv[16];
#pragma unroll
        for (int k = 0; k < IN_DIM; k++) wv[k] = Wih[r * IN_DIM + k];
        wv[5] = 0.0f;                                    // pad slot
#pragma unroll
        for (int j = 0; j < HID; j++) wv[6 + j] = Whh[r * HID + j];
#pragma unroll
        for (int p = 0; p < 8; p++) wp[q][p] = pack2(wv[2 * p], wv[2 * p + 1]);
        bias[q] = bih[r] + bhh[r];
    }

    float c    = cx0[(size_t)b * HID + h];
    float hcur = hx0[(size_t)b * HID + h];

    // Preload x for steps 0..PF-1 into the register ring (raw values; the
    // consumer runs PF steps after the load -> DRAM latency hidden).
    float xr[PF][IN_DIM];
#pragma unroll
    for (int d = 0; d < PF; d++) {
        const float* pp = x + ((size_t)d * BATCH + b) * IN_DIM;
#pragma unroll
        for (int k = 0; k < IN_DIM; k++) xr[d][k] = __ldg(pp + k);
    }

    const size_t xstep = (size_t)BATCH * IN_DIM;
    const float* xpf = x + ((size_t)PF * BATCH + b) * IN_DIM;  // next fetch
    float* op = out + (size_t)b * HID + h;

#pragma unroll 1
    for (int tc = 0; tc < T_STEPS; tc += PF) {
        const bool do_pf = (tc + PF < T_STEPS);          // uniform
#pragma unroll
        for (int d = 0; d < PF; d++) {
            // Consume this slot's raw x (loaded PF steps ago).
            const float x0 = xr[d][0], x1 = xr[d][1], x2 = xr[d][2];
            const float x3 = xr[d][3], x4 = xr[d][4];

            // Issue the prefetch for step tc+d+PF (raw, consumed later).
            if (do_pf) {
#pragma unroll
                for (int k = 0; k < IN_DIM; k++) xr[d][k] = __ldg(xpf + k);
                xpf += xstep;
            }

            // Gather this batch's 10 h values from peer lanes.
            float hv[HID];
#pragma unroll
            for (int j = 0; j < HID; j++)
                hv[j] = __shfl_sync(0xFFFFFFFFu, hcur, base + j);

            const u64 v0 = pack2(x0, x1), v1 = pack2(x2, x3),
                      v2 = pack2(x4, 0.0f);
            u64 hp[5];
#pragma unroll
            for (int p = 0; p < 5; p++) hp[p] = pack2(hv[2 * p], hv[2 * p + 1]);

            float gate[4];
#pragma unroll
            for (int q = 0; q < 4; q++) {
                // x-part (off the h chain: x already in registers)
                u64 accA = pack2(bias[q], 0.0f);
                accA = ffma2(wp[q][0], v0, accA);
                accA = ffma2(wp[q][1], v1, accA);
                accA = ffma2(wp[q][2], v2, accA);
                // h-part split 3+2 to shorten the post-shfl dependency depth
                accA = ffma2(wp[q][3], hp[0], accA);
                accA = ffma2(wp[q][4], hp[1], accA);
                accA = ffma2(wp[q][5], hp[2], accA);
                u64 accB = fmul2(wp[q][6], hp[3]);
                accB = ffma2(wp[q][7], hp[4], accB);
                const u64 acc = fadd2(accA, accB);
                float lo, hi;
                unpack2(acc, lo, hi);
                gate[q] = lo + hi;
            }

            const float is = fsig(gate[0]);
            const float fs = fsig(gate[1]);
            const float gt = tanha(gate[2]);
            const float os = fsig(gate[3]);
            c = fs * c + is * gt;
            const float hn = os * tanha(c);
            hcur = hn;

            if (active) *op = hn;            // coalesced within batch group
            op += (size_t)BATCH * HID;
        }
    }
}

extern "C" void kernel_launch(void* const* d_in, const int* in_sizes, int n_in,
                              void* d_out, int out_size) {
    (void)in_sizes; (void)n_in; (void)out_size;
    const float* x   = (const float*)d_in[0];
    const float* hx0 = (const float*)d_in[1];
    const float* cx0 = (const float*)d_in[2];
    const float* Wih = (const float*)d_in[3];
    const float* Whh = (const float*)d_in[4];
    const float* bih = (const float*)d_in[5];
    const float* bhh = (const float*)d_in[6];
    float* out = (float*)d_out;

    lstm_scan_kernel<<<NBLOCKS, NTHREADS>>>(x, hx0, cx0, Wih, Whh, bih, bhh, out);
}

// round 10
// speedup vs baseline: 2.5931x; 1.5256x over previous
#include <cuda_runtime.h>

// LSTM scan: T=2048, B=2048, IN=5, H=10.
// R5 (resubmit — previous round hit a GB300 container infra failure, kernel
// never ran): geometry + exchange + branch-free hot loop.
//  - 2-warp blocks (342 blocks): ~2.3 warps on each of 2 SMSPs — enough
//    co-residency to hide the serial chain (R4's 1 warp/SMSP was latency-
//    bound), half of R2's single-scheduler issue pileup.
//  - h exchange via double-buffered warp-local smem: STS + syncwarp + 5
//    LDS.64 (pairs land directly as f32x2 operands) instead of 10 SHFLs.
//  - PF=8 raw-x register ring; final chunk peeled -> zero branches in the
//    steady-state step. MUFU.TANH activations, f32x2 gate math.

#define T_STEPS 2048
#define BATCH   2048
#define IN_DIM  5
#define HID     10
#define BPW     3                               // batches per warp (30 lanes)
#define WARPS   2
#define NTHREADS (WARPS * 32)                   // 64
#define BPB     (WARPS * BPW)                   // 6 batches per block
#define NBLOCKS ((BATCH + BPB - 1) / BPB)       // 342
#define PF      8                               // x prefetch depth (divides T)

typedef unsigned long long u64;

__device__ __forceinline__ u64 pack2(float lo, float hi) {
    u64 r;
    asm("mov.b64 %0, {%1, %2};" : "=l"(r) : "f"(lo), "f"(hi));
    return r;
}
__device__ __forceinline__ void unpack2(u64 v, float& lo, float& hi) {
    asm("mov.b64 {%0, %1}, %2;" : "=f"(lo), "=f"(hi) : "l"(v));
}
__device__ __forceinline__ u64 ffma2(u64 a, u64 b, u64 c) {
    u64 d;
    asm("fma.rn.f32x2 %0, %1, %2, %3;" : "=l"(d) : "l"(a), "l"(b), "l"(c));
    return d;
}
__device__ __forceinline__ float tanha(float z) {
    float r;
    asm("tanh.approx.f32 %0, %1;" : "=f"(r) : "f"(z));
    return r;
}
// sigmoid(z) = 0.5 + 0.5*tanh(0.5*z)
__device__ __forceinline__ float fsig(float z) {
    return fmaf(0.5f, tanha(0.5f * z), 0.5f);
}

// One LSTM step. DOPF: issue the x prefetch for PF steps ahead.
// par = d&1 selects the h double-buffer (compile-time after unroll).
#define STEP_BODY(d, DOPF) do {                                               \
    const int par_ = (d) & 1;                                                 \
    float nx0, nx1, nx2, nx3, nx4;                                            \
    if (DOPF) {                       /* compile-time constant */             \
        nx0 = __ldg(xpf + 0); nx1 = __ldg(xpf + 1); nx2 = __ldg(xpf + 2);     \
        nx3 = __ldg(xpf + 3); nx4 = __ldg(xpf + 4);                           \
        xpf += xstep;                                                         \
    }                                                                         \
    __syncwarp();                     /* prev step's h writes -> visible */   \
    const u64 hp0 = rp[par_][0], hp1 = rp[par_][1], hp2 = rp[par_][2];        \
    const u64 hp3 = rp[par_][3], hp4 = rp[par_][4];                           \
    const u64 v0 = pack2(xr[d][0], xr[d][1]);                                 \
    const u64 v1 = pack2(xr[d][2], xr[d][3]);                                 \
    const u64 v2 = pack2(xr[d][4], 0.0f);                                     \
    float gate[4];                                                            \
    _Pragma("unroll")                                                         \
    for (int q = 0; q < 4; q++) {                                             \
        u64 acc = pack2(bias[q], 0.0f);                                       \
        acc = ffma2(wp[q][0], v0, acc);                                       \
        acc = ffma2(wp[q][1], v1, acc);                                       \
        acc = ffma2(wp[q][2], v2, acc);                                       \
        acc = ffma2(wp[q][3], hp0, acc);                                      \
        acc = ffma2(wp[q][4], hp1, acc);                                      \
        acc = ffma2(wp[q][5], hp2, acc);                                      \
        acc = ffma2(wp[q][6], hp3, acc);                                      \
        acc = ffma2(wp[q][7], hp4, acc);                                      \
        float lo_, hi_; unpack2(acc, lo_, hi_);                               \
        gate[q] = lo_ + hi_;                                                  \
    }                                                                         \
    const float is = fsig(gate[0]);                                           \
    const float fs = fsig(gate[1]);                                           \
    const float gt = tanha(gate[2]);                                          \
    const float os = fsig(gate[3]);                                           \
    c = fs * c + is * gt;                                                     \
    const float hn = os * tanha(c);                                           \
    wq[par_ ^ 1][0] = hn;             /* STS into next buffer */              \
    if (active) *op = hn;                                                     \
    op += ostep;                                                              \
    if (DOPF) {                                                               \
        xr[d][0] = nx0; xr[d][1] = nx1; xr[d][2] = nx2;                       \
        xr[d][3] = nx3; xr[d][4] = nx4;                                       \
    }                                                                         \
} while (0)

__global__ void __launch_bounds__(NTHREADS, 1) lstm_scan_kernel(
    const float* __restrict__ x,     // [T, B, IN]
    const float* __restrict__ hx0,   // [B, H]
    const float* __restrict__ cx0,   // [B, H]
    const float* __restrict__ Wih,   // [4H, IN]
    const float* __restrict__ Whh,   // [4H, H]
    const float* __restrict__ bih,   // [4H]
    const float* __restrict__ bhh,   // [4H]
    float* __restrict__ out)         // [T*B, H]
{
    // Double-buffered h, per warp. Group row = 10 floats (8B-aligned) ->
    // pairs read as LDS.64. Banks: groups at words {0-9,10-19,20-29} are
    // disjoint; each LDS.64 is a broadcast within its group: conflict-free.
    __shared__ __align__(16) float hbuf[2][WARPS][32];

    const int lane = threadIdx.x & 31;
    const int warp = threadIdx.x >> 5;
    const int g    = lane / HID;          // batch slot in warp (0..3)
    const int h    = lane % HID;          // hidden unit 0..9

    const int  b_raw  = blockIdx.x * BPB + warp * BPW + g;
    const bool active = (g < BPW) && (b_raw < BATCH);
    const int  b      = active ? b_raw : (BATCH - 1);   // clamp: safe loads

    // Pack weights for v-layout [x0..x4, 0, h0..h9] (16 slots -> 8 f32x2).
    u64 wp[4][8];
    float bias[4];
#pragma unroll
    for (int q = 0; q < 4; q++) {
        const int r = q * HID + h;
        float wv[16];
#pragma unroll
        for (int k = 0; k < IN_DIM; k++) wv[k] = Wih[r * IN_DIM + k];
        wv[5] = 0.0f;                                    // pad slot
#pragma unroll
        for (int j = 0; j < HID; j++) wv[6 + j] = Whh[r * HID + j];
#pragma unroll
        for (int p = 0; p < 8; p++) wp[q][p] = pack2(wv[2 * p], wv[2 * p + 1]);
        bias[q] = bih[r] + bhh[r];
    }

    float c = cx0[(size_t)b * HID + h];

    // Exchange pointers (computed once). Reads use the group row clamped to
    // a valid group; writes by the 2 inactive lanes land at words 30/31
    // (in-bounds, never read).
    const int gr = (g < BPW ? g : BPW - 1) * HID;
    const u64* rp[2] = { (const u64*)&hbuf[0][warp][gr],
                         (const u64*)&hbuf[1][warp][gr] };
    float* wq[2] = { &hbuf[0][warp][g * HID + h],
                     &hbuf[1][warp][g * HID + h] };

    wq[0][0] = hx0[(size_t)b * HID + h];   // initial h into buffer 0

    // Preload x rows 0..PF-1 into the register ring.
    float xr[PF][IN_DIM];
#pragma unroll
    for (int d = 0; d < PF; d++) {
        const float* pp = x + ((size_t)d * BATCH + b) * IN_DIM;
#pragma unroll
        for (int k = 0; k < IN_DIM; k++) xr[d][k] = __ldg(pp + k);
    }

    const size_t xstep = (size_t)BATCH * IN_DIM;
    const size_t ostep = (size_t)BATCH * HID;
    const float* xpf = x + ((size_t)PF * BATCH + b) * IN_DIM;   // next fetch
    float* op = out + (size_t)b * HID + h;

    // Main loop: all chunks except the last prefetch unconditionally.
#pragma unroll 1
    for (int tc = 0; tc < T_STEPS - PF; tc += PF) {
#pragma unroll
        for (int d = 0; d < PF; d++) STEP_BODY(d, true);
    }
    // Peeled final chunk: consume the ring, no prefetch, no branches.
#pragma unroll
    for (int d = 0; d < PF; d++) STEP_BODY(d, false);
}

extern "C" void kernel_launch(void* const* d_in, const int* in_sizes, int n_in,
                              void* d_out, int out_size) {
    (void)in_sizes; (void)n_in; (void)out_size;
    const float* x   = (const float*)d_in[0];
    const float* hx0 = (const float*)d_in[1];
    const float* cx0 = (const float*)d_in[2];
    const float* Wih = (const float*)d_in[3];
    const float* Whh = (const float*)d_in[4];
    const float* bih = (const float*)d_in[5];
    const float* bhh = (const float*)d_in[6];
    float* out = (float*)d_out;

    lstm_scan_kernel<<<NBLOCKS, NTHREADS>>>(x, hx0, cx0, Wih, Whh, bih, bhh, out);
}